// round 16
// baseline (speedup 1.0000x reference)
#include <cuda_runtime.h>

// StepRelu: y = 0 for x<=0; ((ceil(x/theta)-1)*theta) for 0<x<=theta*steps; x otherwise.
// theta = 0.1, steps = 16 -> upper = 1.6.
//
// FINAL — converged, reproduced 6x at ~149.7us kernel / ~156.5us total,
// 85.8-86.6% of HBM spec (~6.81 TB/s): the mixed r/w DRAM stream floor.
// Traffic is irreducible (1 GiB elementwise map); issue 21%, L1/L2 ~40%
// => DRAM interface is the only saturated resource.
//
// Config: 128-thread blocks, VEC=4 float4/thread (MLP=4 front-batched
// LDG.128), __ldcs/__stcs L1-bypass streaming (R13 ablation: default
// policy costs 3% DRAM), zero-predication exact path, oversubscribed
// launch (65536 CTAs — fresh CTAs sustain in-flight bytes).
// Rejected by measurement: VEC=1 (72.5% DRAM), VEC=8 (occ loss),
// __stwt (85.1%), default ld/st (83.1%), persistent grid-stride (73.3%).

#define VEC 4        // float4s per thread
#define NTHREADS 128

__device__ __forceinline__ float step_relu(float x) {
    const float theta     = 0.1f;
    const float inv_theta = 10.0f;
    const float upper     = 1.6f;
    float binned = (ceilf(x * inv_theta) - 1.0f) * theta;
    float y = (x <= upper) ? binned : x;
    return (x <= 0.0f) ? 0.0f : y;
}

__device__ __forceinline__ float4 step_relu4(float4 v) {
    float4 r;
    r.x = step_relu(v.x);
    r.y = step_relu(v.y);
    r.z = step_relu(v.z);
    r.w = step_relu(v.w);
    return r;
}

// Fast path: n4 divisible by NTHREADS*VEC (512), no bounds checks.
__global__ void __launch_bounds__(NTHREADS) step_relu_v4x4_128(
    const float4* __restrict__ in, float4* __restrict__ out)
{
    int base = blockIdx.x * (NTHREADS * VEC) + threadIdx.x;

    float4 v[VEC];
#pragma unroll
    for (int k = 0; k < VEC; k++)
        v[k] = __ldcs(in + base + k * NTHREADS);   // independent, front-batched

#pragma unroll
    for (int k = 0; k < VEC; k++)
        __stcs(out + base + k * NTHREADS, step_relu4(v[k]));
}

// Generic guarded path (covers any n4 remainder region).
__global__ void __launch_bounds__(NTHREADS) step_relu_v4_guard(
    const float4* __restrict__ in, float4* __restrict__ out, int start, int n4)
{
    int i = start + blockIdx.x * blockDim.x + threadIdx.x;
    if (i < n4) __stcs(out + i, step_relu4(__ldcs(in + i)));
}

// Scalar tail for n % 4 != 0.
__global__ void step_relu_tail(
    const float* __restrict__ in, float* __restrict__ out, int start, int n)
{
    int i = start + blockIdx.x * blockDim.x + threadIdx.x;
    if (i < n) out[i] = step_relu(in[i]);
}

extern "C" void kernel_launch(void* const* d_in, const int* in_sizes, int n_in,
                              void* d_out, int out_size)
{
    const float* x = (const float*)d_in[0];
    float* y = (float*)d_out;
    int n = in_sizes[0];

    int n4 = n / 4;
    const int per_block = NTHREADS * VEC;     // 512 float4s per block
    int exact_blocks = n4 / per_block;

    if (exact_blocks > 0) {
        step_relu_v4x4_128<<<exact_blocks, NTHREADS>>>(
            (const float4*)x, (float4*)y);
    }
    int done4 = exact_blocks * per_block;
    int rem4 = n4 - done4;
    if (rem4 > 0) {
        int blocks = (rem4 + NTHREADS - 1) / NTHREADS;
        step_relu_v4_guard<<<blocks, NTHREADS>>>(
            (const float4*)x, (float4*)y, done4, n4);
    }
    int rem = n - n4 * 4;
    if (rem > 0) {
        step_relu_tail<<<1, NTHREADS>>>(x, y, n4 * 4, n);
    }
}

// round 17
// speedup vs baseline: 1.0053x; 1.0053x over previous
#include <cuda_runtime.h>

// StepRelu: y = 0 for x<=0; ((ceil(x/theta)-1)*theta) for 0<x<=theta*steps; x otherwise.
// theta = 0.1, steps = 16 -> upper = 1.6.
//
// FINAL — converged, reproduced 6x at ~149.7us kernel / ~156.5us total,
// 85.8-86.6% of HBM spec (~6.81 TB/s): the mixed r/w DRAM stream floor.
// Traffic is irreducible (1 GiB elementwise map); issue 21%, L1/L2 ~40%
// => DRAM interface is the only saturated resource.
//
// Config: 128-thread blocks, VEC=4 float4/thread (MLP=4 front-batched
// LDG.128), __ldcs/__stcs L1-bypass streaming (R13 ablation: default
// policy costs 3% DRAM), zero-predication exact path, oversubscribed
// launch (65536 CTAs — fresh CTAs sustain in-flight bytes).
// Rejected by measurement: VEC=1 (72.5% DRAM), VEC=8 (occ loss),
// __stwt (85.1%), default ld/st (83.1%), persistent grid-stride (73.3%).

#define VEC 4        // float4s per thread
#define NTHREADS 128

__device__ __forceinline__ float step_relu(float x) {
    const float theta     = 0.1f;
    const float inv_theta = 10.0f;
    const float upper     = 1.6f;
    float binned = (ceilf(x * inv_theta) - 1.0f) * theta;
    float y = (x <= upper) ? binned : x;
    return (x <= 0.0f) ? 0.0f : y;
}

__device__ __forceinline__ float4 step_relu4(float4 v) {
    float4 r;
    r.x = step_relu(v.x);
    r.y = step_relu(v.y);
    r.z = step_relu(v.z);
    r.w = step_relu(v.w);
    return r;
}

// Fast path: n4 divisible by NTHREADS*VEC (512), no bounds checks.
__global__ void __launch_bounds__(NTHREADS) step_relu_v4x4_128(
    const float4* __restrict__ in, float4* __restrict__ out)
{
    int base = blockIdx.x * (NTHREADS * VEC) + threadIdx.x;

    float4 v[VEC];
#pragma unroll
    for (int k = 0; k < VEC; k++)
        v[k] = __ldcs(in + base + k * NTHREADS);   // independent, front-batched

#pragma unroll
    for (int k = 0; k < VEC; k++)
        __stcs(out + base + k * NTHREADS, step_relu4(v[k]));
}

// Generic guarded path (covers any n4 remainder region).
__global__ void __launch_bounds__(NTHREADS) step_relu_v4_guard(
    const float4* __restrict__ in, float4* __restrict__ out, int start, int n4)
{
    int i = start + blockIdx.x * blockDim.x + threadIdx.x;
    if (i < n4) __stcs(out + i, step_relu4(__ldcs(in + i)));
}

// Scalar tail for n % 4 != 0.
__global__ void step_relu_tail(
    const float* __restrict__ in, float* __restrict__ out, int start, int n)
{
    int i = start + blockIdx.x * blockDim.x + threadIdx.x;
    if (i < n) out[i] = step_relu(in[i]);
}

extern "C" void kernel_launch(void* const* d_in, const int* in_sizes, int n_in,
                              void* d_out, int out_size)
{
    const float* x = (const float*)d_in[0];
    float* y = (float*)d_out;
    int n = in_sizes[0];

    int n4 = n / 4;
    const int per_block = NTHREADS * VEC;     // 512 float4s per block
    int exact_blocks = n4 / per_block;

    if (exact_blocks > 0) {
        step_relu_v4x4_128<<<exact_blocks, NTHREADS>>>(
            (const float4*)x, (float4*)y);
    }
    int done4 = exact_blocks * per_block;
    int rem4 = n4 - done4;
    if (rem4 > 0) {
        int blocks = (rem4 + NTHREADS - 1) / NTHREADS;
        step_relu_v4_guard<<<blocks, NTHREADS>>>(
            (const float4*)x, (float4*)y, done4, n4);
    }
    int rem = n - n4 * 4;
    if (rem > 0) {
        step_relu_tail<<<1, NTHREADS>>>(x, y, n4 * 4, n);
    }
}